// round 16
// baseline (speedup 1.0000x reference)
#include <cuda_runtime.h>

#define Bn 16
#define Tn 192
#define Un 64
#define Hn 512
#define NEGF (-1e30f)
#define LOG2E 1.4426950408889634f
#define LN2f  0.6931471805599453f
#define CNTS 257

// Diagonal-major fused table, base-2 log domain. Cell (t,u) at row d=t+u,
// col u, float2: .x = lpb2[t-1][u], .y = lpl2[t][u-1]. OOR cells = NEGF
// (written by t==0 blocks; value identical every replay). +128 floats pad
// so the b=15 consumer's row-256 overread stays in bounds.
__device__ float g_cd[Bn * 256 * Un * 2 + 128];
// Per-(b,row) completion counters (one release-red per contributing warp).
__device__ int g_cnt[Bn * CNTS];

__device__ __forceinline__ void red_release_add1(int* a) {
    asm volatile("red.release.gpu.global.add.u32 [%0], 1;" :: "l"(a) : "memory");
}
__device__ __forceinline__ int ld_acquire(const int* a) {
    int v;
    asm volatile("ld.acquire.gpu.global.u32 %0, [%1];" : "=r"(v) : "l"(a) : "memory");
    return v;
}

__device__ __forceinline__ float warpMax(float v) {
#pragma unroll
    for (int o = 16; o > 0; o >>= 1)
        v = fmaxf(v, __shfl_xor_sync(0xffffffffu, v, o));
    return v;
}
__device__ __forceinline__ float warpSum(float v) {
#pragma unroll
    for (int o = 16; o > 0; o >>= 1)
        v += __shfl_xor_sync(0xffffffffu, v, o);
    return v;
}
__device__ __forceinline__ float ex2f(float x) {
    float r; asm("ex2.approx.ftz.f32 %0, %1;" : "=f"(r) : "f"(x)); return r;
}
__device__ __forceinline__ float lg2f(float x) {
    float r; asm("lg2.approx.ftz.f32 %0, %1;" : "=f"(r) : "f"(x)); return r;
}
__device__ __forceinline__ float laddexp2(float a, float b) {
    float m = fmaxf(a, b);
    float t = ex2f(-fabsf(a - b));
    return m + lg2f(1.0f + t);
}
__device__ __forceinline__ float extract_elem(
    const float4& v0, const float4& v1, const float4& v2, const float4& v3, int e) {
    int g = (e >> 7) & 3;
    int comp = e & 3;
    int srclane = (e >> 2) & 31;
    float4 vv = (g == 0) ? v0 : (g == 1) ? v1 : (g == 2) ? v2 : v3;
    float c = (comp == 0) ? vv.x : (comp == 1) ? vv.y : (comp == 2) ? vv.z : vv.w;
    return __shfl_sync(0xffffffffu, c, srclane);
}

__global__ __launch_bounds__(512, 4)
void k_fused(const float* __restrict__ x,
             const int* __restrict__ label,
             const int* __restrict__ f_len,
             const int* __restrict__ y_len,
             const int* __restrict__ blankp,
             float* __restrict__ out) {
    const int bid = blockIdx.x;
    const int tid = threadIdx.x;
    const int warp = tid >> 5;
    const int lane = tid & 31;
    const unsigned FULL = 0xffffffffu;

    if (bid >= Bn) {
        // ================= LSE role (t-major: rows complete progressively) =
        const int bid2 = bid - Bn;
        const int t = bid2 >> 6;               // 0..191 (outer)
        const int b = (bid2 >> 2) & 15;
        const int q = bid2 & 3;
        const int bt = b * Tn + t;
        const int u = (q << 4) + warp;         // 0..63
        const int blank = blankp ? __ldg(blankp) : 0;

        float* const base = g_cd + (size_t)b * 256 * Un * 2;

        // NEGF init of unwritten cells (t==0 blocks only; disjoint writes)
        if (t == 0) {
#pragma unroll
            for (int h = 0; h < 2; h++) {
                int rr = lane + h * 32;
                int rx = (rr <= u) ? rr : rr + 192;
                base[(rx * Un + u) * 2 + 0] = NEGF;
                if (u >= 1) {
                    int ry = (rr < u) ? rr : rr + 192;
                    base[(ry * Un + u) * 2 + 1] = NEGF;
                }
            }
            if (u == 0) {
#pragma unroll
                for (int h = 0; h < 8; h++)
                    base[((lane + h * 32) * Un) * 2 + 1] = NEGF;
            }
        }

        const float4* r = reinterpret_cast<const float4*>(x)
                          + ((size_t)bt * Un + u) * (Hn / 4);
        float4 a0 = __ldcs(r + lane);
        float4 a1 = __ldcs(r + lane + 32);
        float4 a2 = __ldcs(r + lane + 64);
        float4 a3 = __ldcs(r + lane + 96);

        int lab = (u < Un - 1) ? __ldg(&label[b * (Un - 1) + u]) : 0;

        float m = fmaxf(fmaxf(fmaxf(a0.x, a0.y), fmaxf(a0.z, a0.w)),
                 fmaxf(fmaxf(fmaxf(a1.x, a1.y), fmaxf(a1.z, a1.w)),
                 fmaxf(fmaxf(fmaxf(a2.x, a2.y), fmaxf(a2.z, a2.w)),
                       fmaxf(fmaxf(a3.x, a3.y), fmaxf(a3.z, a3.w)))));
        m = warpMax(m);
        float s = __expf(a0.x - m) + __expf(a0.y - m) + __expf(a0.z - m) + __expf(a0.w - m)
                + __expf(a1.x - m) + __expf(a1.y - m) + __expf(a1.z - m) + __expf(a1.w - m)
                + __expf(a2.x - m) + __expf(a2.y - m) + __expf(a2.z - m) + __expf(a2.w - m)
                + __expf(a3.x - m) + __expf(a3.y - m) + __expf(a3.z - m) + __expf(a3.w - m);
        s = warpSum(s);
        float denom = m + __logf(s);

        float xb = extract_elem(a0, a1, a2, a3, blank);
        float xl = extract_elem(a0, a1, a2, a3, lab);
        if (lane == 0) {
            base[(((t + u + 1) * Un) + u) * 2 + 0] = (xb - denom) * LOG2E;
            if (u < Un - 1)
                base[(((t + u + 1) * Un) + u + 1) * 2 + 1] = (xl - denom) * LOG2E;
        }
        // release: t==0 warps cover their multi-lane NEGF writes with a fence;
        // all other warps need only lane0's own 2 STGs -> release-red alone.
        if (t == 0) { __syncwarp(); __threadfence(); }
        if (lane == 0)
            red_release_add1(&g_cnt[b * CNTS + t + u + 1]);
        return;
    }

    // ================= ALPHA role (b = bid, single warp, producer-paced) ===
    if (tid >= 32) return;
    const int b = bid;
    const int tl = f_len[b] - 1;               // 95..191
    const int ul = y_len[b];                   // 32..63
    const int dHit = tl + ul;                  // 127..254
    int* cnt = g_cnt + b * CNTS;
    const float* gb = g_cd + (size_t)b * 256 * Un * 2;
    const bool hitLane = (lane == (ul >> 1));
    const bool selB = (ul & 1);

    float aA = 0.f, aB = 0.f, res = 0.f;

#pragma unroll 1
    for (int cs = 1; cs <= 225; cs += 32) {    // 8 chunks: rows 1..256
        // warp-parallel poll: lane k gates row cs+k (acquire)
        int rr = cs + lane;
        int tgt = (rr <= 255) ? (min(63, rr - 1) - max(0, rr - 192) + 1) : 0;
        for (;;) {
            bool ok = (rr > 255) || (ld_acquire(cnt + rr) >= tgt);
            if (__all_sync(FULL, ok)) break;
            __nanosleep(200);
        }
        // consume 32 rows; fixed trip count -> LDGs front-batched (<= 32 in flight)
#pragma unroll
        for (int k = 0; k < 32; k++) {
            int dd = cs + k;
            float4 c = __ldg(reinterpret_cast<const float4*>(gb) + dd * 32 + lane);
            float lA = __shfl_up_sync(FULL, aB, 1);  // lane0: dead (c.y == NEGF)
            float lB = aA;
            float vA = laddexp2(aA + c.x, lA + c.y);
            float vB = laddexp2(aB + c.z, lB + c.w);
            aA = vA;
            aB = vB;
            float hv = selB ? vB : vA;
            res = (hitLane && dd == dHit) ? hv : res;
        }
    }

    // all rows 1..255 confirmed -> fin_b safe; row-256 overread was padded/NEGF
    float fin_b = __ldg(gb + ((dHit + 1) * Un + ul) * 2 + 0);
    if (hitLane)
        out[b] = -(res + fin_b) * LN2f;

    // reset counters for the next graph replay (all reds for b have landed)
    __syncwarp();
    for (int i = lane; i < CNTS; i += 32)
        cnt[i] = 0;
}

extern "C" void kernel_launch(void* const* d_in, const int* in_sizes, int n_in,
                              void* d_out, int out_size) {
    const float* x = (const float*)d_in[0];
    const int* label = (const int*)d_in[1];
    const int* f_len = (const int*)d_in[2];
    const int* y_len = (const int*)d_in[3];
    const int* blankp = (n_in > 4) ? (const int*)d_in[4] : nullptr;

    k_fused<<<Bn + Tn * Bn * 4, 512>>>(x, label, f_len, y_len, blankp,
                                       (float*)d_out);
}

// round 17
// speedup vs baseline: 1.1380x; 1.1380x over previous
#include <cuda_runtime.h>

#define Bn 16
#define Tn 192
#define Un 64
#define Hn 512
#define NEGF (-1e30f)
#define LOG2E 1.4426950408889634f
#define LN2f  0.6931471805599453f

// Diagonal-major fused table, base-2 log domain.
// Cell (t,u) lives at row d = t+u, col u, as float2:
//   .x = lpb2[t-1][u]  (the "up" transition into (t,u))
//   .y = lpl2[t][u-1]  (the "left" transition into (t,u))
// Rows 0..255; cells never written by k_lse are set to NEGF by the t==0
// blocks of k_lse itself (disjoint addresses -> no race, no extra launch).
__device__ float g_cd[Bn * 256 * Un * 2];

__device__ __forceinline__ float warpMax(float v) {
#pragma unroll
    for (int o = 16; o > 0; o >>= 1)
        v = fmaxf(v, __shfl_xor_sync(0xffffffffu, v, o));
    return v;
}

__device__ __forceinline__ float warpSum(float v) {
#pragma unroll
    for (int o = 16; o > 0; o >>= 1)
        v += __shfl_xor_sync(0xffffffffu, v, o);
    return v;
}

__device__ __forceinline__ float ex2f(float x) {
    float r; asm("ex2.approx.ftz.f32 %0, %1;" : "=f"(r) : "f"(x)); return r;
}
__device__ __forceinline__ float lg2f(float x) {
    float r; asm("lg2.approx.ftz.f32 %0, %1;" : "=f"(r) : "f"(x)); return r;
}

// base-2 log-add-exp: max(a,b) + log2(1 + 2^(-|a-b|)). NaN-free for finite in.
__device__ __forceinline__ float laddexp2(float a, float b) {
    float m = fmaxf(a, b);
    float t = ex2f(-fabsf(a - b));
    return m + lg2f(1.0f + t);
}

// Extract element e (0..511) of a row held distributed across the warp.
// WARP-COLLECTIVE: all 32 lanes must be active.
__device__ __forceinline__ float extract_elem(
    const float4& v0, const float4& v1, const float4& v2, const float4& v3, int e) {
    int g = (e >> 7) & 3;
    int comp = e & 3;
    int srclane = (e >> 2) & 31;
    float4 vv = (g == 0) ? v0 : (g == 1) ? v1 : (g == 2) ? v2 : v3;
    float c = (comp == 0) ? vv.x : (comp == 1) ? vv.y : (comp == 2) ? vv.z : vv.w;
    return __shfl_sync(0xffffffffu, c, srclane);
}

// Stage 1: per-(b,t,u) logsumexp over H; one row per warp; writes straight
// into the diagonal-major fused table. t==0 blocks additionally NEGF-fill
// the table cells that are never written (guards + out-of-range region).
// NO atomics, NO fences, NO block-wide syncs: pure streaming (87% DRAM).
__global__ __launch_bounds__(512, 4)
void k_lse(const float* __restrict__ x,
           const int* __restrict__ label,
           const int* __restrict__ blankp) {
    const int blk = blockIdx.x;
    const int bt = blk >> 2;                 // b*Tn + t
    const int b = bt / Tn;
    const int t = bt - b * Tn;
    const int warp = threadIdx.x >> 5;
    const int lane = threadIdx.x & 31;
    const int u = ((blk & 3) << 4) + warp;   // 0..63
    const int blank = blankp ? __ldg(blankp) : 0;

    float* const base = g_cd + (size_t)b * 256 * Un * 2;

    // --- NEGF init of unwritten cells (t==0 blocks only; disjoint writes) ---
    if (t == 0) {
#pragma unroll
        for (int h = 0; h < 2; h++) {
            int r = lane + h * 32;                 // 0..63
            int rx = (r <= u) ? r : r + 192;       // .x unwritten: [0,u] U [u+193,255]
            base[(rx * Un + u) * 2 + 0] = NEGF;
            if (u >= 1) {
                int ry = (r < u) ? r : r + 192;    // .y unwritten: [0,u-1] U [u+192,255]
                base[(ry * Un + u) * 2 + 1] = NEGF;
            }
        }
        if (u == 0) {
#pragma unroll
            for (int h = 0; h < 8; h++)            // col 0 .y: all 256 rows
                base[((lane + h * 32) * Un) * 2 + 1] = NEGF;
        }
    }

    const float4* r = reinterpret_cast<const float4*>(x)
                      + ((size_t)bt * Un + u) * (Hn / 4);
    float4 a0 = __ldcs(r + lane);
    float4 a1 = __ldcs(r + lane + 32);
    float4 a2 = __ldcs(r + lane + 64);
    float4 a3 = __ldcs(r + lane + 96);

    int lab = (u < Un - 1) ? __ldg(&label[b * (Un - 1) + u]) : 0;

    float m = fmaxf(fmaxf(fmaxf(a0.x, a0.y), fmaxf(a0.z, a0.w)),
             fmaxf(fmaxf(fmaxf(a1.x, a1.y), fmaxf(a1.z, a1.w)),
             fmaxf(fmaxf(fmaxf(a2.x, a2.y), fmaxf(a2.z, a2.w)),
                   fmaxf(fmaxf(a3.x, a3.y), fmaxf(a3.z, a3.w)))));
    m = warpMax(m);
    float s = __expf(a0.x - m) + __expf(a0.y - m) + __expf(a0.z - m) + __expf(a0.w - m)
            + __expf(a1.x - m) + __expf(a1.y - m) + __expf(a1.z - m) + __expf(a1.w - m)
            + __expf(a2.x - m) + __expf(a2.y - m) + __expf(a2.z - m) + __expf(a2.w - m)
            + __expf(a3.x - m) + __expf(a3.y - m) + __expf(a3.z - m) + __expf(a3.w - m);
    s = warpSum(s);
    float denom = m + __logf(s);

    float xb = extract_elem(a0, a1, a2, a3, blank);
    float xl = extract_elem(a0, a1, a2, a3, lab);
    if (lane == 0) {
        // lpb2[t][u] feeds cell (t+1, u): row (t+1)+u, col u, comp .x
        base[(((t + u + 1) * Un) + u) * 2 + 0] = (xb - denom) * LOG2E;
        // lpl2[t][u] feeds cell (t, u+1): row t+(u+1), col u+1, comp .y
        if (u < Un - 1)
            base[(((t + u + 1) * Un) + u + 1) * 2 + 1] = (xl - denom) * LOG2E;
    }
}

// Stage 2: uniform anti-diagonal wavefront, diagonal-major fused table.
// One block per b; 512 threads preload the full 128KB table into smem with a
// compile-time trip count; warp 0 runs the wavefront with 2 u-cells per lane,
// ONE conflict-free LDS.128 per lane per diagonal, 2-deep prefetch.
// Loop = chunks of 8 with COMPILE-TIME inner bounds (pipelined bodies) and a
// single uniform early-exit check per chunk (skips avg ~64 dead diagonals).
__global__ __launch_bounds__(512, 1)
void k_alpha(const int* __restrict__ f_len,
             const int* __restrict__ y_len,
             float* __restrict__ out) {
    extern __shared__ float sm[];            // 257 rows * 512 B (1 pad row)

    const int b = blockIdx.x;
    const int tid = threadIdx.x;

    {
        const float4* src = reinterpret_cast<const float4*>(g_cd)
                            + (size_t)b * (256 * Un * 2 / 4);
        float4* dst = reinterpret_cast<float4*>(sm);
        const int nv = 256 * Un * 2 / 4;     // 8192 (compile-time)
#pragma unroll 4
        for (int i = tid; i < nv; i += 512)
            dst[i] = src[i];
        // pad row 256 = float4 indices 8192..8223 (32 float4s = 512 B).
        if (tid < 32)
            dst[8192 + tid] = make_float4(NEGF, NEGF, NEGF, NEGF);
    }
    __syncthreads();

    if (tid >= 32) return;
    const int lane = tid;
    const int tl = f_len[b] - 1;             // 95..191
    const int ul = y_len[b];                 // 32..63
    const int dHit = tl + ul;                // diagonal of the target cell
    const unsigned FULL = 0xffffffffu;
    const bool hitLane = (lane == (ul >> 1));
    const bool parityB = (ul & 1);

    // fin_b = lpb2[tl][ul] = cell (tl+1, ul).x = row dHit+1, col ul, .x
    const float fin_b = sm[(((dHit + 1) * Un) + ul) * 2 + 0];

    const float4* p = reinterpret_cast<const float4*>(sm) + 32 + lane; // d=1
    float aA = 0.f;   // alpha2 of u=2*lane on the previous diagonal
    float aB = 0.f;   // alpha2 of u=2*lane+1
    float res = 0.f;

    float4 c  = p[0];                        // row d=1
    float4 c2 = p[32];                       // row d=2
    // chunks of 8 diagonals; 32 chunks cover d = 1..256 (rows padded to 256).
    // Exit when a chunk starts past dHit -> all d <= dHit processed.
#pragma unroll 1
    for (int d0 = 1; d0 <= 249; d0 += 8) {
        if (d0 > dHit) break;                // uniform: dHit same for warp
#pragma unroll
        for (int k = 0; k < 8; k++) {
            int d = d0 + k;
            float4 cn = p[64];               // row d+2 (<=256: padded)
            p += 32;
            float lA = __shfl_up_sync(FULL, aB, 1);  // lane0: dead (c.y==NEGF)
            float lB = aA;
            float vA = laddexp2(aA + c.x, lA + c.y);
            float vB = laddexp2(aB + c.z, lB + c.w);
            aA = vA;
            aB = vB;
            float hv = parityB ? vB : vA;
            res = (hitLane && (d == dHit)) ? hv : res;
            c = c2;
            c2 = cn;
        }
    }

    if (hitLane)
        out[b] = -(res + fin_b) * LN2f;
}

extern "C" void kernel_launch(void* const* d_in, const int* in_sizes, int n_in,
                              void* d_out, int out_size) {
    const float* x = (const float*)d_in[0];
    const int* label = (const int*)d_in[1];
    const int* f_len = (const int*)d_in[2];
    const int* y_len = (const int*)d_in[3];
    const int* blankp = (n_in > 4) ? (const int*)d_in[4] : nullptr;

    k_lse<<<Bn * Tn * 4, 512>>>(x, label, blankp);

    const int smem = 257 * Un * 2 * (int)sizeof(float);  // 131584 B
    cudaFuncSetAttribute(k_alpha, cudaFuncAttributeMaxDynamicSharedMemorySize, smem);
    k_alpha<<<Bn, 512, smem>>>(f_len, y_len, (float*)d_out);
}